// round 15
// baseline (speedup 1.0000x reference)
#include <cuda_runtime.h>
#include <cuda_fp16.h>
#include <math.h>
#include <stdint.h>

#define N_NODES 100000
#define N_EDGES 1600000
#define C_IN 128
#define HID 128
#define N_LAYERS 4
#define N_GRAPHS 512
#define N_OUT 10
#define BN_EPS 1e-5f

// ---------------- scratch (static device allocations) ----------------------
__device__ __half g_xin[(size_t)N_NODES * C_IN];
__device__ __half g_agg[(size_t)N_NODES * C_IN];
__device__ __half g_h1[(size_t)N_NODES * 2 * HID];
__device__ __half g_x[(size_t)N_NODES * HID];
__device__ float g_pooled[N_GRAPHS * HID];
// CSR
__device__ int g_deg[N_NODES];
__device__ int g_rowptr[N_NODES + 1];
__device__ int g_cursor[N_NODES];
__device__ int g_bsum[128];
__device__ int g_csrsrc[N_EDGES];
// transposed fp16 weights: Wt[n][k]
__device__ __half g_w1t[N_LAYERS * 2 * HID * C_IN];
__device__ __half g_w2t[N_LAYERS * HID * 2 * HID];

// ================= helpers =================
__device__ __forceinline__ uint32_t smem_u32(const void* p) {
    uint32_t a;
    asm("{ .reg .u64 t; cvta.to.shared.u64 t, %1; cvt.u32.u64 %0, t; }"
        : "=r"(a) : "l"(p));
    return a;
}
__device__ __forceinline__ uint32_t pack_h2(float a, float b) {
    __half2 t = __floats2half2_rn(a, b);
    return *reinterpret_cast<uint32_t*>(&t);
}
__device__ __forceinline__ float2 unpk(uint32_t u) {
    __half2 t = *reinterpret_cast<__half2*>(&u);
    return __half22float2(t);
}

#define MMA_F16(c, a, b0, b1)                                                \
    asm volatile("mma.sync.aligned.m16n8k16.row.col.f32.f16.f16.f32 "        \
                 "{%0,%1,%2,%3}, {%4,%5,%6,%7}, {%8,%9}, {%0,%1,%2,%3};"     \
                 : "+f"((c)[0]), "+f"((c)[1]), "+f"((c)[2]), "+f"((c)[3])    \
                 : "r"((a)[0]), "r"((a)[1]), "r"((a)[2]), "r"((a)[3]),       \
                   "r"(b0), "r"(b1))

#define LDSM_X4(R, addr)                                                     \
    asm volatile("ldmatrix.sync.aligned.m8n8.x4.shared.b16 "                 \
                 "{%0,%1,%2,%3}, [%4];"                                      \
                 : "=r"((R)[0]), "=r"((R)[1]), "=r"((R)[2]), "=r"((R)[3])    \
                 : "r"(addr))

__device__ __forceinline__ void cp16(uint32_t dst, const void* src, uint32_t sz) {
    asm volatile("cp.async.cg.shared.global [%0], [%1], 16, %2;"
                 :: "r"(dst), "l"(src), "r"(sz) : "memory");
}
#define CP_COMMIT() asm volatile("cp.async.commit_group;" ::: "memory")
#define CP_WAIT(n)  asm volatile("cp.async.wait_group %0;" :: "n"(n) : "memory")

// ---------------- utility kernels -------------------------------------------
__global__ void k_zero_all(int* __restrict__ deg, float* __restrict__ pooled) {
    int i = blockIdx.x * blockDim.x + threadIdx.x;
    if (i < N_NODES) deg[i] = 0;
    if (i < N_GRAPHS * HID) pooled[i] = 0.f;
}
__global__ void k_x2h(const float* __restrict__ x, __half* __restrict__ o) {
    int i = blockIdx.x * blockDim.x + threadIdx.x;
    if (i < N_NODES * C_IN / 4) {
        float4 v = *(const float4*)(x + i * 4);
        *(uint2*)(o + i * 4) = make_uint2(pack_h2(v.x, v.y), pack_h2(v.z, v.w));
    }
}

// ---------------- CSR build -------------------------------------------------
__global__ void k_hist(const int* __restrict__ dst, int* __restrict__ deg) {
    int e = blockIdx.x * blockDim.x + threadIdx.x;
    if (e < N_EDGES) atomicAdd(&deg[dst[e]], 1);
}
__global__ void k_scan_block(const int* __restrict__ deg, int* __restrict__ rowptr,
                             int* __restrict__ bsum) {
    __shared__ int s[1024];
    int gid = blockIdx.x * 1024 + threadIdx.x;
    int v = (gid < N_NODES) ? deg[gid] : 0;
    s[threadIdx.x] = v;
    __syncthreads();
#pragma unroll
    for (int off = 1; off < 1024; off <<= 1) {
        int t = (threadIdx.x >= off) ? s[threadIdx.x - off] : 0;
        __syncthreads();
        s[threadIdx.x] += t;
        __syncthreads();
    }
    if (gid < N_NODES) rowptr[gid] = s[threadIdx.x] - v;
    if (threadIdx.x == 1023) bsum[blockIdx.x] = s[1023];
}
__global__ void k_scan_sums(int* __restrict__ bsum, int nb) {
    if (threadIdx.x == 0) {
        int run = 0;
        for (int i = 0; i < nb; i++) { int t = bsum[i]; bsum[i] = run; run += t; }
    }
}
__global__ void k_scan_add(int* __restrict__ rowptr, const int* __restrict__ bsum,
                           int* __restrict__ cursor) {
    int gid = blockIdx.x * blockDim.x + threadIdx.x;
    if (gid < N_NODES) {
        int v = rowptr[gid] + bsum[gid >> 10];
        rowptr[gid] = v;
        cursor[gid] = v;
    }
    if (gid == 0) rowptr[N_NODES] = N_EDGES;
}
__global__ void k_scatter(const int* __restrict__ src, const int* __restrict__ dst,
                          int* __restrict__ cursor, int* __restrict__ csrsrc) {
    int e = blockIdx.x * blockDim.x + threadIdx.x;
    if (e < N_EDGES) {
        int pos = atomicAdd(&cursor[dst[e]], 1);
        csrsrc[pos] = src[e];
    }
}

// ---------------- weight prep: transpose + fp16 ------------------------------
__global__ void k_prep_w(const float* __restrict__ W, __half* __restrict__ Th,
                         int K, int N) {
    int idx = blockIdx.x * blockDim.x + threadIdx.x;
    if (idx >= K * N) return;
    size_t lofs = (size_t)blockIdx.y * K * N;
    int k = idx / N, n = idx % N;
    Th[lofs + (size_t)n * K + k] = __float2half_rn(W[lofs + idx]);
}

// ---------------- split-warp gather, 8-edge unroll (MLP=4) -------------------
__global__ void k_gather(const __half* __restrict__ x,
                         const int* __restrict__ rowptr,
                         const int* __restrict__ csrsrc,
                         const float* __restrict__ epsp,
                         __half* __restrict__ o) {
    int n = (blockIdx.x * blockDim.x + threadIdx.x) >> 5;
    if (n >= N_NODES) return;
    int lane = threadIdx.x & 31;
    int half = lane >> 4;
    int sl = lane & 15;
    float epsv = 1.0f + __ldg(epsp);
    const uint4* x4 = (const uint4*)x;

    float acc[8];
    if (half == 0) {
        uint4 u = __ldg(x4 + (size_t)n * 16 + sl);
        float2 a0 = unpk(u.x), a1 = unpk(u.y), a2 = unpk(u.z), a3 = unpk(u.w);
        acc[0] = epsv * a0.x; acc[1] = epsv * a0.y;
        acc[2] = epsv * a1.x; acc[3] = epsv * a1.y;
        acc[4] = epsv * a2.x; acc[5] = epsv * a2.y;
        acc[6] = epsv * a3.x; acc[7] = epsv * a3.y;
    } else {
#pragma unroll
        for (int j = 0; j < 8; j++) acc[j] = 0.f;
    }

    int beg = __ldg(rowptr + n), end = __ldg(rowptr + n + 1);
    int e = beg;
    // 8 edges per iteration: 4 independent LDG.128 per lane in flight
    for (; e + 7 < end; e += 8) {
        int s0 = __ldg(csrsrc + e + half);
        int s1 = __ldg(csrsrc + e + 2 + half);
        int s2 = __ldg(csrsrc + e + 4 + half);
        int s3 = __ldg(csrsrc + e + 6 + half);
        uint4 u0 = __ldg(x4 + (size_t)s0 * 16 + sl);
        uint4 u1 = __ldg(x4 + (size_t)s1 * 16 + sl);
        uint4 u2 = __ldg(x4 + (size_t)s2 * 16 + sl);
        uint4 u3 = __ldg(x4 + (size_t)s3 * 16 + sl);
        float2 p0 = unpk(u0.x), p1 = unpk(u0.y), p2 = unpk(u0.z), p3 = unpk(u0.w);
        float2 q0 = unpk(u1.x), q1 = unpk(u1.y), q2 = unpk(u1.z), q3 = unpk(u1.w);
        float2 r0 = unpk(u2.x), r1 = unpk(u2.y), r2 = unpk(u2.z), r3 = unpk(u2.w);
        float2 t0 = unpk(u3.x), t1 = unpk(u3.y), t2 = unpk(u3.z), t3 = unpk(u3.w);
        acc[0] += (p0.x + q0.x) + (r0.x + t0.x);
        acc[1] += (p0.y + q0.y) + (r0.y + t0.y);
        acc[2] += (p1.x + q1.x) + (r1.x + t1.x);
        acc[3] += (p1.y + q1.y) + (r1.y + t1.y);
        acc[4] += (p2.x + q2.x) + (r2.x + t2.x);
        acc[5] += (p2.y + q2.y) + (r2.y + t2.y);
        acc[6] += (p3.x + q3.x) + (r3.x + t3.x);
        acc[7] += (p3.y + q3.y) + (r3.y + t3.y);
    }
    // 4-edge step
    for (; e + 3 < end; e += 4) {
        int s0 = __ldg(csrsrc + e + half);
        int s1 = __ldg(csrsrc + e + 2 + half);
        uint4 u0 = __ldg(x4 + (size_t)s0 * 16 + sl);
        uint4 u1 = __ldg(x4 + (size_t)s1 * 16 + sl);
        float2 p0 = unpk(u0.x), p1 = unpk(u0.y), p2 = unpk(u0.z), p3 = unpk(u0.w);
        float2 q0 = unpk(u1.x), q1 = unpk(u1.y), q2 = unpk(u1.z), q3 = unpk(u1.w);
        acc[0] += p0.x + q0.x; acc[1] += p0.y + q0.y;
        acc[2] += p1.x + q1.x; acc[3] += p1.y + q1.y;
        acc[4] += p2.x + q2.x; acc[5] += p2.y + q2.y;
        acc[6] += p3.x + q3.x; acc[7] += p3.y + q3.y;
    }
    // 2-edge step
    for (; e + 1 < end; e += 2) {
        int s0 = __ldg(csrsrc + e + half);
        uint4 u0 = __ldg(x4 + (size_t)s0 * 16 + sl);
        float2 p0 = unpk(u0.x), p1 = unpk(u0.y), p2 = unpk(u0.z), p3 = unpk(u0.w);
        acc[0] += p0.x; acc[1] += p0.y;
        acc[2] += p1.x; acc[3] += p1.y;
        acc[4] += p2.x; acc[5] += p2.y;
        acc[6] += p3.x; acc[7] += p3.y;
    }
    if (e < end && half == 0) {
        int s0 = __ldg(csrsrc + e);
        uint4 u0 = __ldg(x4 + (size_t)s0 * 16 + sl);
        float2 p0 = unpk(u0.x), p1 = unpk(u0.y), p2 = unpk(u0.z), p3 = unpk(u0.w);
        acc[0] += p0.x; acc[1] += p0.y;
        acc[2] += p1.x; acc[3] += p1.y;
        acc[4] += p2.x; acc[5] += p2.y;
        acc[6] += p3.x; acc[7] += p3.y;
    }
#pragma unroll
    for (int j = 0; j < 8; j++)
        acc[j] += __shfl_xor_sync(0xffffffffu, acc[j], 16);
    if (half == 0) {
        uint4 v;
        v.x = pack_h2(acc[0], acc[1]);
        v.y = pack_h2(acc[2], acc[3]);
        v.z = pack_h2(acc[4], acc[5]);
        v.w = pack_h2(acc[6], acc[7]);
        *(uint4*)(o + (size_t)n * C_IN + sl * 8) = v;
    }
}

// ---------------- cp.async + ldmatrix fp16 GEMM, BK=64 (round-12 core) -------
#define LDT 72                           // 64 + 8 pad
#define TILE_B (128 * LDT * 2)           // 18432 B per matrix
#define OFF_A 0
#define OFF_B TILE_B
#define STG (2 * TILE_B)                 // 36864 B per stage
#define GEMM_SMEM (2 * STG)              // 73728 B -> 2 CTAs/SM

__global__ __launch_bounds__(256)
void k_gemm_mma(const __half* __restrict__ A,
                const __half* __restrict__ B,
                const float* __restrict__ bias,
                const float* __restrict__ bng, const float* __restrict__ bnb,
                const float* __restrict__ bnm, const float* __restrict__ bnv,
                __half* __restrict__ out,
                int M, int Ntot, int K) {
    extern __shared__ __align__(16) char sm[];
    __shared__ float s_sc[128];
    __shared__ float s_sh[128];

    const int tid = threadIdx.x;
    const int wid = tid >> 5;
    const int lane = tid & 31;
    const int warp_m = wid & 3;
    const int warp_n = wid >> 2;
    const int g = lane >> 2;
    const int q = lane & 3;
    const int m0 = blockIdx.x * 128;
    const int n0 = blockIdx.y * 128;
    const uint32_t smb = smem_u32(sm);

    if (tid < 128) {
        int c = n0 + tid;
        float s = __ldg(bng + c) * rsqrtf(__ldg(bnv + c) + BN_EPS);
        s_sc[tid] = s;
        s_sh[tid] = (__ldg(bias + c) - __ldg(bnm + c)) * s + __ldg(bnb + c);
    }

    const uint32_t a_lm = (uint32_t)((warp_m * 32 + (lane & 15)) * LDT + (lane >> 4) * 8) * 2;
    const uint32_t b_lm = (uint32_t)((warp_n * 64 + (lane & 15)) * LDT + (lane >> 4) * 8) * 2;

    float acc[2][8][4];
#pragma unroll
    for (int mt = 0; mt < 2; mt++)
#pragma unroll
        for (int nt = 0; nt < 8; nt++)
#pragma unroll
            for (int j = 0; j < 4; j++) acc[mt][nt][j] = 0.f;

    const int NCH = K >> 6;

    auto prefetch = [&](int c) {
        const uint32_t base = smb + (c & 1) * STG;
        const int k0 = c << 6;
#pragma unroll
        for (int i = 0; i < 4; ++i) {
            int idx = i * 256 + tid;
            int r = idx >> 3;
            int kc = (idx & 7) * 8;
            uint32_t so = (uint32_t)(r * LDT + kc) * 2;
            int row = m0 + r;
            uint32_t sz = (row < M) ? 16u : 0u;
            cp16(base + OFF_A + so, A + (size_t)row * K + k0 + kc, sz);
            cp16(base + OFF_B + so, B + (size_t)(n0 + r) * K + k0 + kc, 16u);
        }
    };

    prefetch(0);
    CP_COMMIT();

    for (int c = 0; c < NCH; ++c) {
        if (c + 1 < NCH) {
            prefetch(c + 1);
            CP_COMMIT();
            CP_WAIT(1);
        } else {
            CP_WAIT(0);
        }
        __syncthreads();
        const uint32_t sb = smb + (c & 1) * STG;
#pragma unroll
        for (int ks = 0; ks < 64; ks += 16) {
            uint32_t ah[2][4];
#pragma unroll
            for (int mt = 0; mt < 2; mt++) {
                uint32_t ao = sb + a_lm + (uint32_t)(mt * 16 * LDT + ks) * 2;
                LDSM_X4(ah[mt], ao + OFF_A);
            }
#pragma unroll
            for (int p = 0; p < 4; p++) {
                uint32_t bh[4];
                uint32_t bo = sb + b_lm + (uint32_t)(p * 16 * LDT + ks) * 2;
                LDSM_X4(bh, bo + OFF_B);
#pragma unroll
                for (int sub = 0; sub < 2; sub++) {
                    int nt = p * 2 + sub;
                    uint32_t b0 = bh[sub], b1 = bh[2 + sub];
#pragma unroll
                    for (int mt = 0; mt < 2; mt++)
                        MMA_F16(acc[mt][nt], ah[mt], b0, b1);
                }
            }
        }
        __syncthreads();
    }

    // ---- epilogue: bias+BN+ReLU -> fp16, smem-staged coalesced stores ----
    uint32_t* smw = (uint32_t*)sm;   // row pitch 68 words
#pragma unroll
    for (int mt = 0; mt < 2; mt++) {
        int rl0 = warp_m * 32 + mt * 16 + g;
#pragma unroll
        for (int nt = 0; nt < 8; nt++) {
            int cl = warp_n * 64 + nt * 8 + q * 2;
            float sc0 = s_sc[cl], sc1 = s_sc[cl + 1];
            float sh0 = s_sh[cl], sh1 = s_sh[cl + 1];
            int wc = cl >> 1;
            const float* a = acc[mt][nt];
#pragma unroll
            for (int h = 0; h < 2; h++) {
                int rl = rl0 + h * 8;
                float o0 = fmaxf(fmaf(a[2 * h + 0], sc0, sh0), 0.f);
                float o1 = fmaxf(fmaf(a[2 * h + 1], sc1, sh1), 0.f);
                smw[rl * 68 + wc] = pack_h2(o0, o1);
            }
        }
    }
    __syncthreads();
#pragma unroll
    for (int i = 0; i < 8; i++) {
        int idx = i * 256 + tid;
        int r = idx >> 4;            // 0..127
        int co = (idx & 15) * 8;     // 0..120
        if (m0 + r < M) {
            uint4 v = *(const uint4*)(smw + r * 68 + (co >> 1));
            *(uint4*)(out + (size_t)(m0 + r) * Ntot + n0 + co) = v;
        }
    }
}

// ---------------- graph pooling (fp16 x input) -------------------------------
__global__ void k_pool(const __half* __restrict__ x,
                       const int* __restrict__ batch,
                       float* __restrict__ pooled) {
    int n = (blockIdx.x * blockDim.x + threadIdx.x) >> 5;
    if (n >= N_NODES) return;
    int lane = threadIdx.x & 31;
    const uint2* x2 = (const uint2*)x;
    uint2 u = __ldg(x2 + (size_t)n * 32 + lane);
    float2 h0 = unpk(u.x), h1 = unpk(u.y);
    int gph = __ldg(batch + n);
    float* op = pooled + (size_t)gph * HID + lane * 4;
    asm volatile("red.global.add.v4.f32 [%0], {%1,%2,%3,%4};"
                 :: "l"(op), "f"(h0.x), "f"(h0.y), "f"(h1.x), "f"(h1.y)
                 : "memory");
}

// ---------------- head ------------------------------------------------------
__global__ void k_head(const float* __restrict__ pooled,
                       const float* __restrict__ lw1, const float* __restrict__ lb1,
                       const float* __restrict__ g3, const float* __restrict__ b3,
                       const float* __restrict__ m3, const float* __restrict__ v3,
                       const float* __restrict__ lw2, const float* __restrict__ lb2,
                       float* __restrict__ out) {
    __shared__ float p[HID];
    __shared__ float h[HID];
    __shared__ float lg[N_OUT];
    __shared__ float red2[2];
    int gph = blockIdx.x;
    int t = threadIdx.x;

    p[t] = pooled[gph * HID + t];
    __syncthreads();

    float acc = __ldg(lb1 + t);
#pragma unroll 8
    for (int k = 0; k < HID; k++) acc = fmaf(p[k], __ldg(lw1 + k * HID + t), acc);
    float s = __ldg(g3 + t) * rsqrtf(__ldg(v3 + t) + BN_EPS);
    acc = (acc - __ldg(m3 + t)) * s + __ldg(b3 + t);
    h[t] = fmaxf(acc, 0.f);
    __syncthreads();

    if (t < N_OUT) {
        float a = __ldg(lb2 + t);
#pragma unroll 8
        for (int k = 0; k < HID; k++) a = fmaf(h[k], __ldg(lw2 + k * N_OUT + t), a);
        lg[t] = a;
    }
    __syncthreads();

    if (t == 0) {
        float mx = lg[0];
        for (int i = 1; i < N_OUT; i++) mx = fmaxf(mx, lg[i]);
        float se = 0.f;
        for (int i = 0; i < N_OUT; i++) se += expf(lg[i] - mx);
        red2[0] = mx;
        red2[1] = logf(se);
    }
    __syncthreads();

    if (t < N_OUT) out[gph * N_OUT + t] = lg[t] - red2[0] - red2[1];
}

// ---------------- host orchestration ----------------------------------------
extern "C" void kernel_launch(void* const* d_in, const int* in_sizes, int n_in,
                              void* d_out, int out_size) {
    const float* x       = (const float*)d_in[0];
    const int*   ei      = (const int*)d_in[1];
    const int*   batch   = (const int*)d_in[2];
    const float* w1      = (const float*)d_in[3];
    const float* b1      = (const float*)d_in[4];
    const float* bn1_g   = (const float*)d_in[5];
    const float* bn1_b   = (const float*)d_in[6];
    const float* bn1_m   = (const float*)d_in[7];
    const float* bn1_v   = (const float*)d_in[8];
    const float* gin_eps = (const float*)d_in[9];
    const float* w2      = (const float*)d_in[10];
    const float* b2      = (const float*)d_in[11];
    const float* bn2_g   = (const float*)d_in[12];
    const float* bn2_b   = (const float*)d_in[13];
    const float* bn2_m   = (const float*)d_in[14];
    const float* bn2_v   = (const float*)d_in[15];
    const float* lin1_w  = (const float*)d_in[16];
    const float* lin1_b  = (const float*)d_in[17];
    const float* bn3_g   = (const float*)d_in[18];
    const float* bn3_b   = (const float*)d_in[19];
    const float* bn3_m   = (const float*)d_in[20];
    const float* bn3_v   = (const float*)d_in[21];
    const float* lin2_w  = (const float*)d_in[22];
    const float* lin2_b  = (const float*)d_in[23];

    __half *xin, *agg, *h1, *xh, *w1t, *w2t;
    float* pooled;
    int *deg, *rowptr, *cursor, *bsum, *csrsrc;
    cudaGetSymbolAddress((void**)&xin, g_xin);
    cudaGetSymbolAddress((void**)&agg, g_agg);
    cudaGetSymbolAddress((void**)&h1, g_h1);
    cudaGetSymbolAddress((void**)&xh, g_x);
    cudaGetSymbolAddress((void**)&pooled, g_pooled);
    cudaGetSymbolAddress((void**)&deg, g_deg);
    cudaGetSymbolAddress((void**)&rowptr, g_rowptr);
    cudaGetSymbolAddress((void**)&cursor, g_cursor);
    cudaGetSymbolAddress((void**)&bsum, g_bsum);
    cudaGetSymbolAddress((void**)&csrsrc, g_csrsrc);
    cudaGetSymbolAddress((void**)&w1t, g_w1t);
    cudaGetSymbolAddress((void**)&w2t, g_w2t);

    cudaFuncSetAttribute(k_gemm_mma, cudaFuncAttributeMaxDynamicSharedMemorySize,
                         GEMM_SMEM);

    const int WSZ = C_IN * 2 * HID;
    const int NB = (N_NODES + 1023) / 1024;

    k_zero_all<<<(N_NODES + 255) / 256, 256>>>(deg, pooled);
    k_x2h<<<(N_NODES * C_IN / 4 + 255) / 256, 256>>>(x, xin);
    {
        dim3 gr((WSZ + 255) / 256, N_LAYERS);
        k_prep_w<<<gr, 256>>>(w1, w1t, C_IN, 2 * HID);
        k_prep_w<<<gr, 256>>>(w2, w2t, 2 * HID, HID);
    }

    // --- CSR build ---
    k_hist<<<(N_EDGES + 255) / 256, 256>>>(ei + N_EDGES, deg);
    k_scan_block<<<NB, 1024>>>(deg, rowptr, bsum);
    k_scan_sums<<<1, 32>>>(bsum, NB);
    k_scan_add<<<(N_NODES + 255) / 256, 256>>>(rowptr, bsum, cursor);
    k_scatter<<<(N_EDGES + 255) / 256, 256>>>(ei, ei + N_EDGES, cursor, csrsrc);

    const int MT = (N_NODES + 127) / 128;
    const int GB = (N_NODES * 32 + 255) / 256;

    for (int l = 0; l < N_LAYERS; l++) {
        const __half* xl = (l == 0) ? xin : xh;
        k_gather<<<GB, 256>>>(xl, rowptr, csrsrc, gin_eps + l, agg);
        // GEMM1: [100000,128]@[128,256] -> h1 (fp16), BN1+ReLU
        {
            dim3 grid(MT, 2);
            k_gemm_mma<<<grid, 256, GEMM_SMEM>>>(
                agg, w1t + (size_t)l * WSZ,
                b1 + (size_t)l * 2 * HID,
                bn1_g + (size_t)l * 2 * HID, bn1_b + (size_t)l * 2 * HID,
                bn1_m + (size_t)l * 2 * HID, bn1_v + (size_t)l * 2 * HID,
                h1, N_NODES, 2 * HID, C_IN);
        }
        // GEMM2: [100000,256]@[256,128] -> x (fp16), BN2+ReLU
        {
            dim3 grid(MT, 1);
            k_gemm_mma<<<grid, 256, GEMM_SMEM>>>(
                h1, w2t + (size_t)l * WSZ,
                b2 + (size_t)l * HID,
                bn2_g + (size_t)l * HID, bn2_b + (size_t)l * HID,
                bn2_m + (size_t)l * HID, bn2_v + (size_t)l * HID,
                xh, N_NODES, HID, 2 * HID);
        }
    }

    k_pool<<<GB, 256>>>(xh, batch, pooled);
    k_head<<<N_GRAPHS, HID>>>(pooled, lin1_w, lin1_b,
                              bn3_g, bn3_b, bn3_m, bn3_v,
                              lin2_w, lin2_b, (float*)d_out);
}

// round 16
// speedup vs baseline: 1.1101x; 1.1101x over previous
#include <cuda_runtime.h>
#include <cuda_fp16.h>
#include <math.h>
#include <stdint.h>

#define N_NODES 100000
#define N_EDGES 1600000
#define C_IN 128
#define HID 128
#define N_LAYERS 4
#define N_GRAPHS 512
#define N_OUT 10
#define BN_EPS 1e-5f

// ---------------- scratch (static device allocations) ----------------------
__device__ __half g_xin[(size_t)N_NODES * C_IN];
__device__ __half g_agg[(size_t)N_NODES * C_IN];
__device__ __half g_h1[(size_t)N_NODES * 2 * HID];
__device__ __half g_x[(size_t)N_NODES * HID];
__device__ float g_pooled[N_GRAPHS * HID];
// CSR
__device__ int g_deg[N_NODES];
__device__ int g_rowptr[N_NODES + 1];
__device__ int g_cursor[N_NODES];
__device__ int g_bsum[128];
__device__ int g_csrsrc[N_EDGES];
// transposed fp16 weights: Wt[n][k]
__device__ __half g_w1t[N_LAYERS * 2 * HID * C_IN];
__device__ __half g_w2t[N_LAYERS * HID * 2 * HID];

// ================= helpers =================
__device__ __forceinline__ uint32_t smem_u32(const void* p) {
    uint32_t a;
    asm("{ .reg .u64 t; cvta.to.shared.u64 t, %1; cvt.u32.u64 %0, t; }"
        : "=r"(a) : "l"(p));
    return a;
}
__device__ __forceinline__ uint32_t pack_h2(float a, float b) {
    __half2 t = __floats2half2_rn(a, b);
    return *reinterpret_cast<uint32_t*>(&t);
}
__device__ __forceinline__ float2 unpk(uint32_t u) {
    __half2 t = *reinterpret_cast<__half2*>(&u);
    return __half22float2(t);
}

#define MMA_F16(c, a, b0, b1)                                                \
    asm volatile("mma.sync.aligned.m16n8k16.row.col.f32.f16.f16.f32 "        \
                 "{%0,%1,%2,%3}, {%4,%5,%6,%7}, {%8,%9}, {%0,%1,%2,%3};"     \
                 : "+f"((c)[0]), "+f"((c)[1]), "+f"((c)[2]), "+f"((c)[3])    \
                 : "r"((a)[0]), "r"((a)[1]), "r"((a)[2]), "r"((a)[3]),       \
                   "r"(b0), "r"(b1))

#define LDSM_X4(R, addr)                                                     \
    asm volatile("ldmatrix.sync.aligned.m8n8.x4.shared.b16 "                 \
                 "{%0,%1,%2,%3}, [%4];"                                      \
                 : "=r"((R)[0]), "=r"((R)[1]), "=r"((R)[2]), "=r"((R)[3])    \
                 : "r"(addr))

__device__ __forceinline__ void cp16(uint32_t dst, const void* src, uint32_t sz) {
    asm volatile("cp.async.cg.shared.global [%0], [%1], 16, %2;"
                 :: "r"(dst), "l"(src), "r"(sz) : "memory");
}
#define CP_COMMIT() asm volatile("cp.async.commit_group;" ::: "memory")
#define CP_WAIT(n)  asm volatile("cp.async.wait_group %0;" :: "n"(n) : "memory")

// ---------------- merged prolog: zero + x->fp16 + weight prep ---------------
// Disjoint regions, one launch. Grid sized by x2h work (3.2M items).
__global__ void k_prep_all(const float* __restrict__ x, __half* __restrict__ xin,
                           const float* __restrict__ w1, __half* __restrict__ w1t,
                           const float* __restrict__ w2, __half* __restrict__ w2t,
                           int* __restrict__ deg, float* __restrict__ pooled) {
    int i = blockIdx.x * blockDim.x + threadIdx.x;
    // x2h: 100000*128/4 = 3,200,000 groups of 4 floats
    if (i < N_NODES * C_IN / 4) {
        float4 v = *(const float4*)(x + (size_t)i * 4);
        *(uint2*)(xin + (size_t)i * 4) = make_uint2(pack_h2(v.x, v.y), pack_h2(v.z, v.w));
    }
    if (i < N_NODES) deg[i] = 0;
    if (i < N_GRAPHS * HID) pooled[i] = 0.f;
    // weight prep: w1 [L][128][256] -> w1t [L][256][128]; 131072 elems total
    const int WSZ = C_IN * 2 * HID;  // 32768 per layer
    if (i < N_LAYERS * WSZ) {
        int l = i / WSZ, idx = i % WSZ;
        int k = idx / (2 * HID), n = idx % (2 * HID);
        size_t lofs = (size_t)l * WSZ;
        w1t[lofs + (size_t)n * C_IN + k] = __float2half_rn(w1[lofs + idx]);
    }
    if (i >= N_LAYERS * WSZ && i < 2 * N_LAYERS * WSZ) {
        int j = i - N_LAYERS * WSZ;
        int l = j / WSZ, idx = j % WSZ;
        int k = idx / HID, n = idx % HID;
        size_t lofs = (size_t)l * WSZ;
        w2t[lofs + (size_t)n * (2 * HID) + k] = __float2half_rn(w2[lofs + idx]);
    }
}

// ---------------- CSR build -------------------------------------------------
__global__ void k_hist(const int* __restrict__ dst, int* __restrict__ deg) {
    int e = blockIdx.x * blockDim.x + threadIdx.x;
    if (e < N_EDGES) atomicAdd(&deg[dst[e]], 1);
}
__global__ void k_scan_block(const int* __restrict__ deg, int* __restrict__ rowptr,
                             int* __restrict__ bsum) {
    __shared__ int s[1024];
    int gid = blockIdx.x * 1024 + threadIdx.x;
    int v = (gid < N_NODES) ? deg[gid] : 0;
    s[threadIdx.x] = v;
    __syncthreads();
#pragma unroll
    for (int off = 1; off < 1024; off <<= 1) {
        int t = (threadIdx.x >= off) ? s[threadIdx.x - off] : 0;
        __syncthreads();
        s[threadIdx.x] += t;
        __syncthreads();
    }
    if (gid < N_NODES) rowptr[gid] = s[threadIdx.x] - v;
    if (threadIdx.x == 1023) bsum[blockIdx.x] = s[1023];
}
__global__ void k_scan_sums(int* __restrict__ bsum, int nb) {
    if (threadIdx.x == 0) {
        int run = 0;
        for (int i = 0; i < nb; i++) { int t = bsum[i]; bsum[i] = run; run += t; }
    }
}
__global__ void k_scan_add(int* __restrict__ rowptr, const int* __restrict__ bsum,
                           int* __restrict__ cursor) {
    int gid = blockIdx.x * blockDim.x + threadIdx.x;
    if (gid < N_NODES) {
        int v = rowptr[gid] + bsum[gid >> 10];
        rowptr[gid] = v;
        cursor[gid] = v;
    }
    if (gid == 0) rowptr[N_NODES] = N_EDGES;
}
__global__ void k_scatter(const int* __restrict__ src, const int* __restrict__ dst,
                          int* __restrict__ cursor, int* __restrict__ csrsrc) {
    int e = blockIdx.x * blockDim.x + threadIdx.x;
    if (e < N_EDGES) {
        int pos = atomicAdd(&cursor[dst[e]], 1);
        csrsrc[pos] = src[e];
    }
}

// ---------------- split-warp gather (round-12 proven version) ----------------
__global__ void k_gather(const __half* __restrict__ x,
                         const int* __restrict__ rowptr,
                         const int* __restrict__ csrsrc,
                         const float* __restrict__ epsp,
                         __half* __restrict__ o) {
    int n = (blockIdx.x * blockDim.x + threadIdx.x) >> 5;
    if (n >= N_NODES) return;
    int lane = threadIdx.x & 31;
    int half = lane >> 4;
    int sl = lane & 15;
    float epsv = 1.0f + __ldg(epsp);
    const uint4* x4 = (const uint4*)x;

    float acc[8];
    if (half == 0) {
        uint4 u = __ldg(x4 + (size_t)n * 16 + sl);
        float2 a0 = unpk(u.x), a1 = unpk(u.y), a2 = unpk(u.z), a3 = unpk(u.w);
        acc[0] = epsv * a0.x; acc[1] = epsv * a0.y;
        acc[2] = epsv * a1.x; acc[3] = epsv * a1.y;
        acc[4] = epsv * a2.x; acc[5] = epsv * a2.y;
        acc[6] = epsv * a3.x; acc[7] = epsv * a3.y;
    } else {
#pragma unroll
        for (int j = 0; j < 8; j++) acc[j] = 0.f;
    }

    int beg = __ldg(rowptr + n), end = __ldg(rowptr + n + 1);
    int e = beg;
    for (; e + 3 < end; e += 4) {
        int s0 = __ldg(csrsrc + e + half);
        int s1 = __ldg(csrsrc + e + 2 + half);
        uint4 u0 = __ldg(x4 + (size_t)s0 * 16 + sl);
        uint4 u1 = __ldg(x4 + (size_t)s1 * 16 + sl);
        float2 p0 = unpk(u0.x), p1 = unpk(u0.y), p2 = unpk(u0.z), p3 = unpk(u0.w);
        float2 q0 = unpk(u1.x), q1 = unpk(u1.y), q2 = unpk(u1.z), q3 = unpk(u1.w);
        acc[0] += p0.x + q0.x; acc[1] += p0.y + q0.y;
        acc[2] += p1.x + q1.x; acc[3] += p1.y + q1.y;
        acc[4] += p2.x + q2.x; acc[5] += p2.y + q2.y;
        acc[6] += p3.x + q3.x; acc[7] += p3.y + q3.y;
    }
    for (; e + 1 < end; e += 2) {
        int s0 = __ldg(csrsrc + e + half);
        uint4 u0 = __ldg(x4 + (size_t)s0 * 16 + sl);
        float2 p0 = unpk(u0.x), p1 = unpk(u0.y), p2 = unpk(u0.z), p3 = unpk(u0.w);
        acc[0] += p0.x; acc[1] += p0.y;
        acc[2] += p1.x; acc[3] += p1.y;
        acc[4] += p2.x; acc[5] += p2.y;
        acc[6] += p3.x; acc[7] += p3.y;
    }
    if (e < end && half == 0) {
        int s0 = __ldg(csrsrc + e);
        uint4 u0 = __ldg(x4 + (size_t)s0 * 16 + sl);
        float2 p0 = unpk(u0.x), p1 = unpk(u0.y), p2 = unpk(u0.z), p3 = unpk(u0.w);
        acc[0] += p0.x; acc[1] += p0.y;
        acc[2] += p1.x; acc[3] += p1.y;
        acc[4] += p2.x; acc[5] += p2.y;
        acc[6] += p3.x; acc[7] += p3.y;
    }
#pragma unroll
    for (int j = 0; j < 8; j++)
        acc[j] += __shfl_xor_sync(0xffffffffu, acc[j], 16);
    if (half == 0) {
        uint4 v;
        v.x = pack_h2(acc[0], acc[1]);
        v.y = pack_h2(acc[2], acc[3]);
        v.z = pack_h2(acc[4], acc[5]);
        v.w = pack_h2(acc[6], acc[7]);
        *(uint4*)(o + (size_t)n * C_IN + sl * 8) = v;
    }
}

// ---------------- cp.async + ldmatrix fp16 GEMM, BK=64 (round-12 core) -------
#define LDT 72                           // 64 + 8 pad
#define TILE_B (128 * LDT * 2)           // 18432 B per matrix
#define OFF_A 0
#define OFF_B TILE_B
#define STG (2 * TILE_B)                 // 36864 B per stage
#define GEMM_SMEM (2 * STG)              // 73728 B -> 2 CTAs/SM

__global__ __launch_bounds__(256)
void k_gemm_mma(const __half* __restrict__ A,
                const __half* __restrict__ B,
                const float* __restrict__ bias,
                const float* __restrict__ bng, const float* __restrict__ bnb,
                const float* __restrict__ bnm, const float* __restrict__ bnv,
                __half* __restrict__ out,
                int M, int Ntot, int K) {
    extern __shared__ __align__(16) char sm[];
    __shared__ float s_sc[128];
    __shared__ float s_sh[128];

    const int tid = threadIdx.x;
    const int wid = tid >> 5;
    const int lane = tid & 31;
    const int warp_m = wid & 3;
    const int warp_n = wid >> 2;
    const int g = lane >> 2;
    const int q = lane & 3;
    const int m0 = blockIdx.x * 128;
    const int n0 = blockIdx.y * 128;
    const uint32_t smb = smem_u32(sm);

    if (tid < 128) {
        int c = n0 + tid;
        float s = __ldg(bng + c) * rsqrtf(__ldg(bnv + c) + BN_EPS);
        s_sc[tid] = s;
        s_sh[tid] = (__ldg(bias + c) - __ldg(bnm + c)) * s + __ldg(bnb + c);
    }

    const uint32_t a_lm = (uint32_t)((warp_m * 32 + (lane & 15)) * LDT + (lane >> 4) * 8) * 2;
    const uint32_t b_lm = (uint32_t)((warp_n * 64 + (lane & 15)) * LDT + (lane >> 4) * 8) * 2;

    float acc[2][8][4];
#pragma unroll
    for (int mt = 0; mt < 2; mt++)
#pragma unroll
        for (int nt = 0; nt < 8; nt++)
#pragma unroll
            for (int j = 0; j < 4; j++) acc[mt][nt][j] = 0.f;

    const int NCH = K >> 6;

    auto prefetch = [&](int c) {
        const uint32_t base = smb + (c & 1) * STG;
        const int k0 = c << 6;
#pragma unroll
        for (int i = 0; i < 4; ++i) {
            int idx = i * 256 + tid;
            int r = idx >> 3;
            int kc = (idx & 7) * 8;
            uint32_t so = (uint32_t)(r * LDT + kc) * 2;
            int row = m0 + r;
            uint32_t sz = (row < M) ? 16u : 0u;
            cp16(base + OFF_A + so, A + (size_t)row * K + k0 + kc, sz);
            cp16(base + OFF_B + so, B + (size_t)(n0 + r) * K + k0 + kc, 16u);
        }
    };

    prefetch(0);
    CP_COMMIT();

    for (int c = 0; c < NCH; ++c) {
        if (c + 1 < NCH) {
            prefetch(c + 1);
            CP_COMMIT();
            CP_WAIT(1);
        } else {
            CP_WAIT(0);
        }
        __syncthreads();
        const uint32_t sb = smb + (c & 1) * STG;
#pragma unroll
        for (int ks = 0; ks < 64; ks += 16) {
            uint32_t ah[2][4];
#pragma unroll
            for (int mt = 0; mt < 2; mt++) {
                uint32_t ao = sb + a_lm + (uint32_t)(mt * 16 * LDT + ks) * 2;
                LDSM_X4(ah[mt], ao + OFF_A);
            }
#pragma unroll
            for (int p = 0; p < 4; p++) {
                uint32_t bh[4];
                uint32_t bo = sb + b_lm + (uint32_t)(p * 16 * LDT + ks) * 2;
                LDSM_X4(bh, bo + OFF_B);
#pragma unroll
                for (int sub = 0; sub < 2; sub++) {
                    int nt = p * 2 + sub;
                    uint32_t b0 = bh[sub], b1 = bh[2 + sub];
#pragma unroll
                    for (int mt = 0; mt < 2; mt++)
                        MMA_F16(acc[mt][nt], ah[mt], b0, b1);
                }
            }
        }
        __syncthreads();
    }

    // ---- epilogue: bias+BN+ReLU -> fp16, smem-staged coalesced stores ----
    uint32_t* smw = (uint32_t*)sm;   // row pitch 68 words
#pragma unroll
    for (int mt = 0; mt < 2; mt++) {
        int rl0 = warp_m * 32 + mt * 16 + g;
#pragma unroll
        for (int nt = 0; nt < 8; nt++) {
            int cl = warp_n * 64 + nt * 8 + q * 2;
            float sc0 = s_sc[cl], sc1 = s_sc[cl + 1];
            float sh0 = s_sh[cl], sh1 = s_sh[cl + 1];
            int wc = cl >> 1;
            const float* a = acc[mt][nt];
#pragma unroll
            for (int h = 0; h < 2; h++) {
                int rl = rl0 + h * 8;
                float o0 = fmaxf(fmaf(a[2 * h + 0], sc0, sh0), 0.f);
                float o1 = fmaxf(fmaf(a[2 * h + 1], sc1, sh1), 0.f);
                smw[rl * 68 + wc] = pack_h2(o0, o1);
            }
        }
    }
    __syncthreads();
#pragma unroll
    for (int i = 0; i < 8; i++) {
        int idx = i * 256 + tid;
        int r = idx >> 4;            // 0..127
        int co = (idx & 15) * 8;     // 0..120
        if (m0 + r < M) {
            uint4 v = *(const uint4*)(smw + r * 68 + (co >> 1));
            *(uint4*)(out + (size_t)(m0 + r) * Ntot + n0 + co) = v;
        }
    }
}

// ---------------- graph pooling (fp16 x input) -------------------------------
__global__ void k_pool(const __half* __restrict__ x,
                       const int* __restrict__ batch,
                       float* __restrict__ pooled) {
    int n = (blockIdx.x * blockDim.x + threadIdx.x) >> 5;
    if (n >= N_NODES) return;
    int lane = threadIdx.x & 31;
    const uint2* x2 = (const uint2*)x;
    uint2 u = __ldg(x2 + (size_t)n * 32 + lane);
    float2 h0 = unpk(u.x), h1 = unpk(u.y);
    int gph = __ldg(batch + n);
    float* op = pooled + (size_t)gph * HID + lane * 4;
    asm volatile("red.global.add.v4.f32 [%0], {%1,%2,%3,%4};"
                 :: "l"(op), "f"(h0.x), "f"(h0.y), "f"(h1.x), "f"(h1.y)
                 : "memory");
}

// ---------------- head ------------------------------------------------------
__global__ void k_head(const float* __restrict__ pooled,
                       const float* __restrict__ lw1, const float* __restrict__ lb1,
                       const float* __restrict__ g3, const float* __restrict__ b3,
                       const float* __restrict__ m3, const float* __restrict__ v3,
                       const float* __restrict__ lw2, const float* __restrict__ lb2,
                       float* __restrict__ out) {
    __shared__ float p[HID];
    __shared__ float h[HID];
    __shared__ float lg[N_OUT];
    __shared__ float red2[2];
    int gph = blockIdx.x;
    int t = threadIdx.x;

    p[t] = pooled[gph * HID + t];
    __syncthreads();

    float acc = __ldg(lb1 + t);
#pragma unroll 8
    for (int k = 0; k < HID; k++) acc = fmaf(p[k], __ldg(lw1 + k * HID + t), acc);
    float s = __ldg(g3 + t) * rsqrtf(__ldg(v3 + t) + BN_EPS);
    acc = (acc - __ldg(m3 + t)) * s + __ldg(b3 + t);
    h[t] = fmaxf(acc, 0.f);
    __syncthreads();

    if (t < N_OUT) {
        float a = __ldg(lb2 + t);
#pragma unroll 8
        for (int k = 0; k < HID; k++) a = fmaf(h[k], __ldg(lw2 + k * N_OUT + t), a);
        lg[t] = a;
    }
    __syncthreads();

    if (t == 0) {
        float mx = lg[0];
        for (int i = 1; i < N_OUT; i++) mx = fmaxf(mx, lg[i]);
        float se = 0.f;
        for (int i = 0; i < N_OUT; i++) se += expf(lg[i] - mx);
        red2[0] = mx;
        red2[1] = logf(se);
    }
    __syncthreads();

    if (t < N_OUT) out[gph * N_OUT + t] = lg[t] - red2[0] - red2[1];
}

// ---------------- host orchestration ----------------------------------------
extern "C" void kernel_launch(void* const* d_in, const int* in_sizes, int n_in,
                              void* d_out, int out_size) {
    const float* x       = (const float*)d_in[0];
    const int*   ei      = (const int*)d_in[1];
    const int*   batch   = (const int*)d_in[2];
    const float* w1      = (const float*)d_in[3];
    const float* b1      = (const float*)d_in[4];
    const float* bn1_g   = (const float*)d_in[5];
    const float* bn1_b   = (const float*)d_in[6];
    const float* bn1_m   = (const float*)d_in[7];
    const float* bn1_v   = (const float*)d_in[8];
    const float* gin_eps = (const float*)d_in[9];
    const float* w2      = (const float*)d_in[10];
    const float* b2      = (const float*)d_in[11];
    const float* bn2_g   = (const float*)d_in[12];
    const float* bn2_b   = (const float*)d_in[13];
    const float* bn2_m   = (const float*)d_in[14];
    const float* bn2_v   = (const float*)d_in[15];
    const float* lin1_w  = (const float*)d_in[16];
    const float* lin1_b  = (const float*)d_in[17];
    const float* bn3_g   = (const float*)d_in[18];
    const float* bn3_b   = (const float*)d_in[19];
    const float* bn3_m   = (const float*)d_in[20];
    const float* bn3_v   = (const float*)d_in[21];
    const float* lin2_w  = (const float*)d_in[22];
    const float* lin2_b  = (const float*)d_in[23];

    __half *xin, *agg, *h1, *xh, *w1t, *w2t;
    float* pooled;
    int *deg, *rowptr, *cursor, *bsum, *csrsrc;
    cudaGetSymbolAddress((void**)&xin, g_xin);
    cudaGetSymbolAddress((void**)&agg, g_agg);
    cudaGetSymbolAddress((void**)&h1, g_h1);
    cudaGetSymbolAddress((void**)&xh, g_x);
    cudaGetSymbolAddress((void**)&pooled, g_pooled);
    cudaGetSymbolAddress((void**)&deg, g_deg);
    cudaGetSymbolAddress((void**)&rowptr, g_rowptr);
    cudaGetSymbolAddress((void**)&cursor, g_cursor);
    cudaGetSymbolAddress((void**)&bsum, g_bsum);
    cudaGetSymbolAddress((void**)&csrsrc, g_csrsrc);
    cudaGetSymbolAddress((void**)&w1t, g_w1t);
    cudaGetSymbolAddress((void**)&w2t, g_w2t);

    cudaFuncSetAttribute(k_gemm_mma, cudaFuncAttributeMaxDynamicSharedMemorySize,
                         GEMM_SMEM);

    const int WSZ = C_IN * 2 * HID;
    const int NB = (N_NODES + 1023) / 1024;

    // merged prolog: zero + x2h + both weight preps (one launch)
    k_prep_all<<<(N_NODES * C_IN / 4 + 255) / 256, 256>>>(
        x, xin, w1, w1t, w2, w2t, deg, pooled);

    // --- CSR build ---
    k_hist<<<(N_EDGES + 255) / 256, 256>>>(ei + N_EDGES, deg);
    k_scan_block<<<NB, 1024>>>(deg, rowptr, bsum);
    k_scan_sums<<<1, 32>>>(bsum, NB);
    k_scan_add<<<(N_NODES + 255) / 256, 256>>>(rowptr, bsum, cursor);
    k_scatter<<<(N_EDGES + 255) / 256, 256>>>(ei, ei + N_EDGES, cursor, csrsrc);

    const int MT = (N_NODES + 127) / 128;
    const int GB = (N_NODES * 32 + 255) / 256;

    for (int l = 0; l < N_LAYERS; l++) {
        const __half* xl = (l == 0) ? xin : xh;
        k_gather<<<GB, 256>>>(xl, rowptr, csrsrc, gin_eps + l, agg);
        // GEMM1: [100000,128]@[128,256] -> h1 (fp16), BN1+ReLU
        {
            dim3 grid(MT, 2);
            k_gemm_mma<<<grid, 256, GEMM_SMEM>>>(
                agg, w1t + (size_t)l * WSZ,
                b1 + (size_t)l * 2 * HID,
                bn1_g + (size_t)l * 2 * HID, bn1_b + (size_t)l * 2 * HID,
                bn1_m + (size_t)l * 2 * HID, bn1_v + (size_t)l * 2 * HID,
                h1, N_NODES, 2 * HID, C_IN);
        }
        // GEMM2: [100000,256]@[256,128] -> x (fp16), BN2+ReLU
        {
            dim3 grid(MT, 1);
            k_gemm_mma<<<grid, 256, GEMM_SMEM>>>(
                h1, w2t + (size_t)l * WSZ,
                b2 + (size_t)l * HID,
                bn2_g + (size_t)l * HID, bn2_b + (size_t)l * HID,
                bn2_m + (size_t)l * HID, bn2_v + (size_t)l * HID,
                xh, N_NODES, HID, 2 * HID);
        }
    }

    k_pool<<<GB, 256>>>(xh, batch, pooled);
    k_head<<<N_GRAPHS, HID>>>(pooled, lin1_w, lin1_b,
                              bn3_g, bn3_b, bn3_m, bn3_v,
                              lin2_w, lin2_b, (float*)d_out);
}